// round 1
// baseline (speedup 1.0000x reference)
#include <cuda_runtime.h>
#include <math.h>

#define Nn 50000
#define Mm 800000

// ---------------- scratch (device globals; no allocs allowed) ----------------
__device__ float g_Pmsg[(size_t)Nn * 128];
__device__ float g_Patt[(size_t)Nn * 128];
__device__ float g_agg[(size_t)Nn * 128];
__device__ float g_W1node[258 * 256];
__device__ float g_W1ef[32 * 256];
__device__ float g_G1[(size_t)Nn * 384];
__device__ float g_G2[(size_t)Nn * 384];

__device__ __forceinline__ void red_add4(float* p, float a, float b, float c, float d) {
    asm volatile("red.global.add.v4.f32 [%0], {%1,%2,%3,%4};"
                 :: "l"(p), "f"(a), "f"(b), "f"(c), "f"(d) : "memory");
}

// ---------------- weight repack ----------------
// W1node[258][256]: rows = [state(0:128), attr_e(160:288), attr_n(288:290)] of msg/att w1
//                   cols = [msg(0:128) | att(128:256)]
// W1ef[32][256]: rows 128:160 of w1
__global__ void prep_weights(const float* __restrict__ msg_w1, const float* __restrict__ att_w1) {
    int i = blockIdx.x * blockDim.x + threadIdx.x;
    if (i < 258 * 256) {
        int r = i >> 8;
        int c = i & 255;
        int rr = (r < 128) ? r : (r < 256 ? r + 32 : (r == 256 ? 288 : 289));
        float v = (c < 128) ? msg_w1[rr * 128 + c] : att_w1[rr * 128 + (c - 128)];
        g_W1node[i] = v;
    }
    int j = i - 258 * 256;
    if (j >= 0 && j < 32 * 256) {
        int r = j >> 8;
        int c = j & 255;
        int rr = 128 + r;
        float v = (c < 128) ? msg_w1[rr * 128 + c] : att_w1[rr * 128 + (c - 128)];
        g_W1ef[j] = v;
    }
}

__global__ void clear_agg() {
    int i = blockIdx.x * blockDim.x + threadIdx.x;   // over N*128/4 float4s (exact)
    float4 z = {0.f, 0.f, 0.f, 0.f};
    *(float4*)&g_agg[(size_t)i * 4] = z;
}

// ---------------- node precompute GEMM: [N,258] x [258,256] ----------------
// A gathered on the fly from node_feat / edge_attr / node_attr. blockIdx.y picks msg/att half.
__global__ void __launch_bounds__(256) node_pre(const float* __restrict__ node_feat,
                                                const float* __restrict__ edge_attr,
                                                const float* __restrict__ node_attr) {
    __shared__ float As[16][136];   // [k][row]
    __shared__ float Bs[16][128];
    int tid = threadIdx.x, tx = tid & 15, ty = tid >> 4;
    int rb = blockIdx.x * 128;
    const float* Wb = g_W1node + blockIdx.y * 128;
    float acc[8][8];
#pragma unroll
    for (int r = 0; r < 8; ++r)
#pragma unroll
        for (int j = 0; j < 8; ++j) acc[r][j] = 0.f;

    for (int kt = 0; kt < 17; ++kt) {
        int k0 = kt * 16;
        __syncthreads();
        for (int i = tid; i < 128 * 16; i += 256) {
            int row = i >> 4, k = i & 15;
            int kg = k0 + k;
            int v = rb + row;
            float val = 0.f;
            if (v < Nn && kg < 258) {
                if (kg < 128)       val = node_feat[(size_t)v * 128 + kg];
                else if (kg < 256)  val = edge_attr[(size_t)v * 128 + (kg - 128)];
                else if (kg == 256) val = node_attr[v];
                else                val = node_attr[Nn + v];
            }
            As[k][row] = val;
        }
        for (int i = tid; i < 16 * 128; i += 256) {
            int k = i >> 7, c = i & 127;
            int kg = k0 + k;
            Bs[k][c] = (kg < 258) ? Wb[(size_t)kg * 256 + c] : 0.f;
        }
        __syncthreads();
#pragma unroll
        for (int k = 0; k < 16; ++k) {
            float a[8], b[8];
            *(float4*)(a)     = *(float4*)&As[k][ty * 8];
            *(float4*)(a + 4) = *(float4*)&As[k][ty * 8 + 4];
            *(float4*)(b)     = *(float4*)&Bs[k][tx * 8];
            *(float4*)(b + 4) = *(float4*)&Bs[k][tx * 8 + 4];
#pragma unroll
            for (int r = 0; r < 8; ++r)
#pragma unroll
                for (int j = 0; j < 8; ++j) acc[r][j] = fmaf(a[r], b[j], acc[r][j]);
        }
    }
    float* outp = (blockIdx.y == 0) ? g_Pmsg : g_Patt;
#pragma unroll
    for (int r = 0; r < 8; ++r) {
        int v = rb + ty * 8 + r;
        if (v < Nn) {
            float4 o0 = {acc[r][0], acc[r][1], acc[r][2], acc[r][3]};
            float4 o1 = {acc[r][4], acc[r][5], acc[r][6], acc[r][7]};
            *(float4*)&outp[(size_t)v * 128 + tx * 8]     = o0;
            *(float4*)&outp[(size_t)v * 128 + tx * 8 + 4] = o1;
        }
    }
}

// ---------------- edge kernel ----------------
// per block: 128 edges. z1 = P[src]-P[dst] + ef@W1ef + b1 ; h=relu ; out = h@W2 (+b2)
// pass0 = msg (kept in regs), pass1 = att (sigmoid, multiply, vector-red into g_agg[dst])
#define SMEM_EDGE_FLOATS (16896 + 4608 + 4096)
__global__ void __launch_bounds__(256, 1) edge_kernel(
    const int* __restrict__ edge, const float* __restrict__ edge_feat,
    const float* __restrict__ msg_b1, const float* __restrict__ msg_w2, const float* __restrict__ msg_b2,
    const float* __restrict__ att_b1, const float* __restrict__ att_w2, const float* __restrict__ att_b2) {
    extern __shared__ float smem[];
    float* s_h  = smem;                    // 128*132
    float* s_ef = smem + 16896;            // 128*36
    float* s_w  = smem + 16896 + 4608;     // 32*128
    int* s_src  = (int*)(smem + SMEM_EDGE_FLOATS);
    int* s_dst  = s_src + 128;

    int tid = threadIdx.x;
    int tx = tid & 15, ty = tid >> 4;
    size_t e0 = (size_t)blockIdx.x * 128;

    if (tid < 128) {
        int2 p = ((const int2*)edge)[e0 + tid];
        s_src[tid] = p.x;
        s_dst[tid] = p.y;
    }
    for (int i = tid; i < 128 * 8; i += 256) {
        int e = i >> 3, q = i & 7;
        float4 v = ((const float4*)edge_feat)[(e0 + e) * 8 + q];
        *(float4*)&s_ef[e * 36 + q * 4] = v;
    }

    const int c0 = tx * 8;
    const int r0 = ty * 8;
    float keep[64];

    for (int pass = 0; pass < 2; ++pass) {
        const float* P  = pass ? g_Patt : g_Pmsg;
        const float* b1 = pass ? att_b1 : msg_b1;
        const float* w2 = pass ? att_w2 : msg_w2;
        const float* b2 = pass ? att_b2 : msg_b2;

        __syncthreads();
        for (int i = tid; i < 1024; i += 256) {     // stage W1ef (32x128) for this pass
            int r = i >> 5, q = i & 31;
            *(float4*)&s_w[r * 128 + q * 4] = *(const float4*)&g_W1ef[r * 256 + pass * 128 + q * 4];
        }
        __syncthreads();

        float acc[64];
        {
            float bias8[8];
#pragma unroll
            for (int j = 0; j < 8; ++j) bias8[j] = b1[c0 + j];
#pragma unroll
            for (int r = 0; r < 8; ++r) {
                int e = r0 + r;
                const float* ps = P + (size_t)s_src[e] * 128 + c0;
                const float* pd = P + (size_t)s_dst[e] * 128 + c0;
                float4 a0 = *(const float4*)(ps);
                float4 a1 = *(const float4*)(ps + 4);
                float4 d0 = *(const float4*)(pd);
                float4 d1 = *(const float4*)(pd + 4);
                acc[r * 8 + 0] = a0.x - d0.x + bias8[0];
                acc[r * 8 + 1] = a0.y - d0.y + bias8[1];
                acc[r * 8 + 2] = a0.z - d0.z + bias8[2];
                acc[r * 8 + 3] = a0.w - d0.w + bias8[3];
                acc[r * 8 + 4] = a1.x - d1.x + bias8[4];
                acc[r * 8 + 5] = a1.y - d1.y + bias8[5];
                acc[r * 8 + 6] = a1.z - d1.z + bias8[6];
                acc[r * 8 + 7] = a1.w - d1.w + bias8[7];
            }
        }
#pragma unroll 8
        for (int k = 0; k < 32; ++k) {
            float w[8];
            *(float4*)(w)     = *(float4*)&s_w[k * 128 + c0];
            *(float4*)(w + 4) = *(float4*)&s_w[k * 128 + c0 + 4];
#pragma unroll
            for (int r = 0; r < 8; ++r) {
                float ef = s_ef[(r0 + r) * 36 + k];
#pragma unroll
                for (int j = 0; j < 8; ++j) acc[r * 8 + j] = fmaf(ef, w[j], acc[r * 8 + j]);
            }
        }
#pragma unroll
        for (int r = 0; r < 8; ++r) {   // relu -> s_h
            float4 h0, h1;
            h0.x = fmaxf(acc[r * 8 + 0], 0.f); h0.y = fmaxf(acc[r * 8 + 1], 0.f);
            h0.z = fmaxf(acc[r * 8 + 2], 0.f); h0.w = fmaxf(acc[r * 8 + 3], 0.f);
            h1.x = fmaxf(acc[r * 8 + 4], 0.f); h1.y = fmaxf(acc[r * 8 + 5], 0.f);
            h1.z = fmaxf(acc[r * 8 + 6], 0.f); h1.w = fmaxf(acc[r * 8 + 7], 0.f);
            *(float4*)&s_h[(r0 + r) * 132 + c0]     = h0;
            *(float4*)&s_h[(r0 + r) * 132 + c0 + 4] = h1;
        }
        __syncthreads();

        float outv[64];
#pragma unroll
        for (int i = 0; i < 64; ++i) outv[i] = 0.f;
        for (int kt = 0; kt < 4; ++kt) {
            for (int i = tid; i < 1024; i += 256) {   // stage W2 k-tile (32x128)
                int r = i >> 5, q = i & 31;
                *(float4*)&s_w[r * 128 + q * 4] = *(const float4*)&w2[(kt * 32 + r) * 128 + q * 4];
            }
            __syncthreads();
#pragma unroll
            for (int k4 = 0; k4 < 8; ++k4) {
                float wv[32];
#pragma unroll
                for (int q = 0; q < 4; ++q) {
                    *(float4*)&wv[q * 8]     = *(float4*)&s_w[(k4 * 4 + q) * 128 + c0];
                    *(float4*)&wv[q * 8 + 4] = *(float4*)&s_w[(k4 * 4 + q) * 128 + c0 + 4];
                }
#pragma unroll
                for (int r = 0; r < 8; ++r) {
                    float4 hv = *(float4*)&s_h[(r0 + r) * 132 + kt * 32 + k4 * 4];
#pragma unroll
                    for (int j = 0; j < 8; ++j) {
                        float o = outv[r * 8 + j];
                        o = fmaf(hv.x, wv[0 * 8 + j], o);
                        o = fmaf(hv.y, wv[1 * 8 + j], o);
                        o = fmaf(hv.z, wv[2 * 8 + j], o);
                        o = fmaf(hv.w, wv[3 * 8 + j], o);
                        outv[r * 8 + j] = o;
                    }
                }
            }
            __syncthreads();
        }

        float b2r[8];
#pragma unroll
        for (int j = 0; j < 8; ++j) b2r[j] = b2[c0 + j];
        if (pass == 0) {
#pragma unroll
            for (int i = 0; i < 64; ++i) keep[i] = outv[i] + b2r[i & 7];
        } else {
#pragma unroll
            for (int r = 0; r < 8; ++r) {
                int e = r0 + r;
                float* ap = g_agg + (size_t)s_dst[e] * 128 + c0;
                float m[8];
#pragma unroll
                for (int j = 0; j < 8; ++j) {
                    float z = outv[r * 8 + j] + b2r[j];
                    float att = 1.f / (1.f + __expf(-z));
                    m[j] = keep[r * 8 + j] * att;
                }
                red_add4(ap,     m[0], m[1], m[2], m[3]);
                red_add4(ap + 4, m[4], m[5], m[6], m[7]);
            }
        }
    }
}

// ---------------- GRU GEMMs: G[v][j] = sum_k A[v][k] * W[j][k] + bias[j] ----------------
// mode 0: A = Ain(node_feat) -> g_G2 ; mode 1: A = g_agg -> g_G1
__global__ void __launch_bounds__(256) gemm_tn(const float* __restrict__ Ain,
                                               const float* __restrict__ W,
                                               const float* __restrict__ bias, int mode) {
    __shared__ float As[16][136];
    __shared__ float Bs[16][136];
    const float* A = mode ? g_agg : Ain;
    float* G = mode ? g_G1 : g_G2;
    int tid = threadIdx.x, tx = tid & 15, ty = tid >> 4;
    int rb = blockIdx.x * 128;
    int jb = blockIdx.y * 128;
    float acc[8][8];
#pragma unroll
    for (int r = 0; r < 8; ++r)
#pragma unroll
        for (int j = 0; j < 8; ++j) acc[r][j] = 0.f;

    for (int kt = 0; kt < 8; ++kt) {
        int k0 = kt * 16;
        __syncthreads();
        for (int i = tid; i < 2048; i += 256) {
            int row = i >> 4, k = i & 15;
            int v = rb + row;
            As[k][row] = (v < Nn) ? A[(size_t)v * 128 + k0 + k] : 0.f;
        }
        for (int i = tid; i < 2048; i += 256) {
            int j = i >> 4, k = i & 15;
            Bs[k][j] = W[(size_t)(jb + j) * 128 + k0 + k];
        }
        __syncthreads();
#pragma unroll
        for (int k = 0; k < 16; ++k) {
            float a[8], b[8];
            *(float4*)(a)     = *(float4*)&As[k][ty * 8];
            *(float4*)(a + 4) = *(float4*)&As[k][ty * 8 + 4];
            *(float4*)(b)     = *(float4*)&Bs[k][tx * 8];
            *(float4*)(b + 4) = *(float4*)&Bs[k][tx * 8 + 4];
#pragma unroll
            for (int r = 0; r < 8; ++r)
#pragma unroll
                for (int j = 0; j < 8; ++j) acc[r][j] = fmaf(a[r], b[j], acc[r][j]);
        }
    }
    float br[8];
#pragma unroll
    for (int j = 0; j < 8; ++j) br[j] = bias[jb + tx * 8 + j];
#pragma unroll
    for (int r = 0; r < 8; ++r) {
        int v = rb + ty * 8 + r;
        if (v < Nn) {
            float4 o0 = {acc[r][0] + br[0], acc[r][1] + br[1], acc[r][2] + br[2], acc[r][3] + br[3]};
            float4 o1 = {acc[r][4] + br[4], acc[r][5] + br[5], acc[r][6] + br[6], acc[r][7] + br[7]};
            *(float4*)&G[(size_t)v * 384 + jb + tx * 8]     = o0;
            *(float4*)&G[(size_t)v * 384 + jb + tx * 8 + 4] = o1;
        }
    }
}

// ---------------- gate / output ----------------
__device__ __forceinline__ float gatef(float ir, float iz, float in_, float hr, float hz, float hn, float s) {
    float r = 1.f / (1.f + __expf(-(ir + hr)));
    float z = 1.f / (1.f + __expf(-(iz + hz)));
    float n = tanhf(in_ + r * hn);
    return (1.f - z) * n + z * s;
}
__global__ void gate_kernel(const float* __restrict__ state, float* __restrict__ out) {
    int i = blockIdx.x * blockDim.x + threadIdx.x;   // over N*32 (exact)
    int v = i >> 5;
    int q = (i & 31) * 4;
    const float4 ir = *(const float4*)&g_G1[(size_t)v * 384 + q];
    const float4 iz = *(const float4*)&g_G1[(size_t)v * 384 + 128 + q];
    const float4 in_ = *(const float4*)&g_G1[(size_t)v * 384 + 256 + q];
    const float4 hr = *(const float4*)&g_G2[(size_t)v * 384 + q];
    const float4 hz = *(const float4*)&g_G2[(size_t)v * 384 + 128 + q];
    const float4 hn = *(const float4*)&g_G2[(size_t)v * 384 + 256 + q];
    const float4 s  = *(const float4*)&state[(size_t)v * 128 + q];
    float4 o;
    o.x = gatef(ir.x, iz.x, in_.x, hr.x, hz.x, hn.x, s.x);
    o.y = gatef(ir.y, iz.y, in_.y, hr.y, hz.y, hn.y, s.y);
    o.z = gatef(ir.z, iz.z, in_.z, hr.z, hz.z, hn.z, s.z);
    o.w = gatef(ir.w, iz.w, in_.w, hr.w, hz.w, hn.w, s.w);
    *(float4*)&out[(size_t)v * 128 + q] = o;
}

// ---------------- launch ----------------
extern "C" void kernel_launch(void* const* d_in, const int* in_sizes, int n_in,
                              void* d_out, int out_size) {
    const float* node_feat = (const float*)d_in[0];
    const int*   edge      = (const int*)d_in[1];
    const float* edge_feat = (const float*)d_in[2];
    const float* node_attr = (const float*)d_in[3];
    const float* edge_attr = (const float*)d_in[4];
    const float* msg_w1 = (const float*)d_in[5];
    const float* msg_b1 = (const float*)d_in[6];
    const float* msg_w2 = (const float*)d_in[7];
    const float* msg_b2 = (const float*)d_in[8];
    const float* att_w1 = (const float*)d_in[9];
    const float* att_b1 = (const float*)d_in[10];
    const float* att_w2 = (const float*)d_in[11];
    const float* att_b2 = (const float*)d_in[12];
    const float* gru_w_ih = (const float*)d_in[13];
    const float* gru_w_hh = (const float*)d_in[14];
    const float* gru_b_ih = (const float*)d_in[15];
    const float* gru_b_hh = (const float*)d_in[16];
    float* out = (float*)d_out;

    int smem_edge = SMEM_EDGE_FLOATS * 4 + 256 * 4;
    cudaFuncSetAttribute(edge_kernel, cudaFuncAttributeMaxDynamicSharedMemorySize, smem_edge);

    prep_weights<<<290, 256>>>(msg_w1, att_w1);
    clear_agg<<<6250, 256>>>();
    node_pre<<<dim3(391, 2), 256>>>(node_feat, edge_attr, node_attr);
    gemm_tn<<<dim3(391, 3), 256>>>(node_feat, gru_w_hh, gru_b_hh, 0);   // G2 = state @ Whh^T
    edge_kernel<<<6250, 256, smem_edge>>>(edge, edge_feat,
                                          msg_b1, msg_w2, msg_b2,
                                          att_b1, att_w2, att_b2);
    gemm_tn<<<dim3(391, 3), 256>>>(nullptr, gru_w_ih, gru_b_ih, 1);     // G1 = agg @ Wih^T
    gate_kernel<<<6250, 256>>>(node_feat, out);
}

// round 2
// speedup vs baseline: 1.2960x; 1.2960x over previous
#include <cuda_runtime.h>
#include <math.h>

#define Nn 50000
#define Mm 800000

// ---------------- scratch (device globals; no allocs allowed) ----------------
__device__ float g_Pmsg[(size_t)Nn * 128];
__device__ float g_Patt[(size_t)Nn * 128];
__device__ float g_agg[(size_t)Nn * 128];
__device__ float g_W1node[258 * 256];
__device__ float g_W1efT[2 * 128 * 32];    // [pass][n][k], tf32-rounded
__device__ float g_W2T[2 * 128 * 128];     // [pass][n][k], tf32-rounded
__device__ float g_G1[(size_t)Nn * 384];
__device__ float g_G2[(size_t)Nn * 384];

__device__ __forceinline__ void red_add4(float* p, float a, float b, float c, float d) {
    asm volatile("red.global.add.v4.f32 [%0], {%1,%2,%3,%4};"
                 :: "l"(p), "f"(a), "f"(b), "f"(c), "f"(d) : "memory");
}
__device__ __forceinline__ unsigned f2tf(float x) {
    unsigned r;
    asm("cvt.rna.tf32.f32 %0, %1;" : "=r"(r) : "f"(x));
    return r;
}
__device__ __forceinline__ void mma_tf32(float* d, const unsigned* a, const unsigned* b) {
    asm volatile(
        "mma.sync.aligned.m16n8k8.row.col.f32.tf32.tf32.f32 "
        "{%0,%1,%2,%3},{%4,%5,%6,%7},{%8,%9},{%0,%1,%2,%3};"
        : "+f"(d[0]), "+f"(d[1]), "+f"(d[2]), "+f"(d[3])
        : "r"(a[0]), "r"(a[1]), "r"(a[2]), "r"(a[3]), "r"(b[0]), "r"(b[1]));
}

// ---------------- weight repack (fp32 node precompute weights) ----------------
__global__ void prep_weights(const float* __restrict__ msg_w1, const float* __restrict__ att_w1) {
    int i = blockIdx.x * blockDim.x + threadIdx.x;
    if (i < 258 * 256) {
        int r = i >> 8;
        int c = i & 255;
        int rr = (r < 128) ? r : (r < 256 ? r + 32 : (r == 256 ? 288 : 289));
        float v = (c < 128) ? msg_w1[rr * 128 + c] : att_w1[rr * 128 + (c - 128)];
        g_W1node[i] = v;
    }
}

// ---------------- tf32 weight repack for the edge mma kernel ----------------
// g_W1efT[p][n][k] = w1[(128+k)][n] ; g_W2T[p][n][k] = w2[k][n]  (both tf32-rounded)
__global__ void prep_mma(const float* __restrict__ msg_w1, const float* __restrict__ att_w1,
                         const float* __restrict__ msg_w2, const float* __restrict__ att_w2) {
    int i = blockIdx.x * blockDim.x + threadIdx.x;
    if (i < 2 * 128 * 32) {
        int p = i >> 12;
        int rem = i & 4095;
        int n = rem >> 5, k = rem & 31;
        const float* w1 = p ? att_w1 : msg_w1;
        g_W1efT[i] = __uint_as_float(f2tf(w1[(128 + k) * 128 + n]));
    }
    int j = i - 2 * 128 * 32;
    if (j >= 0 && j < 2 * 128 * 128) {
        int p = j >> 14;
        int rem = j & 16383;
        int n = rem >> 7, k = rem & 127;
        const float* w2 = p ? att_w2 : msg_w2;
        g_W2T[j] = __uint_as_float(f2tf(w2[k * 128 + n]));
    }
}

__global__ void clear_agg() {
    int i = blockIdx.x * blockDim.x + threadIdx.x;
    float4 z = {0.f, 0.f, 0.f, 0.f};
    *(float4*)&g_agg[(size_t)i * 4] = z;
}

// ---------------- node precompute GEMM: [N,258] x [258,256] (fp32) ----------------
__global__ void __launch_bounds__(256) node_pre(const float* __restrict__ node_feat,
                                                const float* __restrict__ edge_attr,
                                                const float* __restrict__ node_attr) {
    __shared__ float As[16][136];
    __shared__ float Bs[16][128];
    int tid = threadIdx.x, tx = tid & 15, ty = tid >> 4;
    int rb = blockIdx.x * 128;
    const float* Wb = g_W1node + blockIdx.y * 128;
    float acc[8][8];
#pragma unroll
    for (int r = 0; r < 8; ++r)
#pragma unroll
        for (int j = 0; j < 8; ++j) acc[r][j] = 0.f;

    for (int kt = 0; kt < 17; ++kt) {
        int k0 = kt * 16;
        __syncthreads();
        for (int i = tid; i < 128 * 16; i += 256) {
            int row = i >> 4, k = i & 15;
            int kg = k0 + k;
            int v = rb + row;
            float val = 0.f;
            if (v < Nn && kg < 258) {
                if (kg < 128)       val = node_feat[(size_t)v * 128 + kg];
                else if (kg < 256)  val = edge_attr[(size_t)v * 128 + (kg - 128)];
                else if (kg == 256) val = node_attr[v];
                else                val = node_attr[Nn + v];
            }
            As[k][row] = val;
        }
        for (int i = tid; i < 16 * 128; i += 256) {
            int k = i >> 7, c = i & 127;
            int kg = k0 + k;
            Bs[k][c] = (kg < 258) ? Wb[(size_t)kg * 256 + c] : 0.f;
        }
        __syncthreads();
#pragma unroll
        for (int k = 0; k < 16; ++k) {
            float a[8], b[8];
            *(float4*)(a)     = *(float4*)&As[k][ty * 8];
            *(float4*)(a + 4) = *(float4*)&As[k][ty * 8 + 4];
            *(float4*)(b)     = *(float4*)&Bs[k][tx * 8];
            *(float4*)(b + 4) = *(float4*)&Bs[k][tx * 8 + 4];
#pragma unroll
            for (int r = 0; r < 8; ++r)
#pragma unroll
                for (int j = 0; j < 8; ++j) acc[r][j] = fmaf(a[r], b[j], acc[r][j]);
        }
    }
    float* outp = (blockIdx.y == 0) ? g_Pmsg : g_Patt;
#pragma unroll
    for (int r = 0; r < 8; ++r) {
        int v = rb + ty * 8 + r;
        if (v < Nn) {
            float4 o0 = {acc[r][0], acc[r][1], acc[r][2], acc[r][3]};
            float4 o1 = {acc[r][4], acc[r][5], acc[r][6], acc[r][7]};
            *(float4*)&outp[(size_t)v * 128 + tx * 8]     = o0;
            *(float4*)&outp[(size_t)v * 128 + tx * 8 + 4] = o1;
        }
    }
}

// ---------------- edge kernel: tf32 mma ----------------
// smem layout (floats): s_hz[128*132] | s_ef[128*36] | s_w[128*36] | s_src[128] s_dst[128]
#define HZ_OFF 0
#define EF_OFF 16896
#define W_OFF  21504
#define IDX_OFF 26112
#define SMEM_EDGE_BYTES (26112 * 4 + 1024)

__global__ void __launch_bounds__(256, 1) edge_kernel(
    const int* __restrict__ edge, const float* __restrict__ edge_feat,
    const float* __restrict__ msg_b1, const float* __restrict__ msg_b2,
    const float* __restrict__ att_b1, const float* __restrict__ att_b2) {
    extern __shared__ float smem[];
    float* s_hz = smem + HZ_OFF;                 // stride 132
    float* s_ef = smem + EF_OFF;                 // stride 36
    float* s_w  = smem + W_OFF;                  // stride 36
    int* s_src  = (int*)(smem + IDX_OFF);
    int* s_dst  = s_src + 128;

    const unsigned* u_hz = (const unsigned*)s_hz;
    const unsigned* u_ef = (const unsigned*)s_ef;
    const unsigned* u_w  = (const unsigned*)s_w;

    int tid = threadIdx.x;
    int lane = tid & 31;
    int warp = tid >> 5;
    int g  = lane >> 2;       // group id 0..7
    int tq = lane & 3;        // thread-in-group 0..3
    int wm = warp >> 1;       // 0..3  (row block of 32)
    int wn = warp & 1;        // 0..1  (col block of 64)
    size_t e0 = (size_t)blockIdx.x * 128;

    if (tid < 128) {
        int2 p = ((const int2*)edge)[e0 + tid];
        s_src[tid] = p.x;
        s_dst[tid] = p.y;
    }
    // stage edge_feat, tf32-rounded
    for (int i = tid; i < 1024; i += 256) {
        int e = i >> 3, q = i & 7;
        float4 v = ((const float4*)edge_feat)[(e0 + e) * 8 + q];
        v.x = __uint_as_float(f2tf(v.x)); v.y = __uint_as_float(f2tf(v.y));
        v.z = __uint_as_float(f2tf(v.z)); v.w = __uint_as_float(f2tf(v.w));
        *(float4*)&s_ef[e * 36 + q * 4] = v;
    }

    float keep[2][8][4];

    for (int pass = 0; pass < 2; ++pass) {
        const float* P  = pass ? g_Patt : g_Pmsg;
        const float* b1 = pass ? att_b1 : msg_b1;
        const float* b2 = pass ? att_b2 : msg_b2;

        __syncthreads();
        // gather P[src]-P[dst] into s_hz (one warp per edge row -> coalesced)
        for (int i = tid; i < 4096; i += 256) {
            int e = i >> 5, q = i & 31;
            const float* ps = P + (size_t)s_src[e] * 128 + q * 4;
            const float* pd = P + (size_t)s_dst[e] * 128 + q * 4;
            float4 a = *(const float4*)ps;
            float4 d = *(const float4*)pd;
            float4 o = {a.x - d.x, a.y - d.y, a.z - d.z, a.w - d.w};
            *(float4*)&s_hz[e * 132 + q * 4] = o;
        }
        // stage W1efT [128n][32k] -> s_w
        for (int i = tid; i < 1024; i += 256) {
            int n = i >> 3, q = i & 7;
            *(float4*)&s_w[n * 36 + q * 4] = *(const float4*)&g_W1efT[pass * 4096 + n * 32 + q * 4];
        }
        __syncthreads();

        // ---- layer 1: E = ef @ W1ef  (M=128, N=128, K=32) ----
        float acc[2][8][4];
#pragma unroll
        for (int mt = 0; mt < 2; ++mt)
#pragma unroll
            for (int nt = 0; nt < 8; ++nt)
#pragma unroll
                for (int j = 0; j < 4; ++j) acc[mt][nt][j] = 0.f;

#pragma unroll
        for (int kt = 0; kt < 4; ++kt) {
            unsigned a[2][4];
#pragma unroll
            for (int mt = 0; mt < 2; ++mt) {
                int r = wm * 32 + mt * 16 + g;
                a[mt][0] = u_ef[r * 36 + kt * 8 + tq];
                a[mt][1] = u_ef[(r + 8) * 36 + kt * 8 + tq];
                a[mt][2] = u_ef[r * 36 + kt * 8 + tq + 4];
                a[mt][3] = u_ef[(r + 8) * 36 + kt * 8 + tq + 4];
            }
#pragma unroll
            for (int nt = 0; nt < 8; ++nt) {
                int c = wn * 64 + nt * 8 + g;
                unsigned b[2];
                b[0] = u_w[c * 36 + kt * 8 + tq];
                b[1] = u_w[c * 36 + kt * 8 + tq + 4];
                mma_tf32(acc[0][nt], a[0], b);
                mma_tf32(acc[1][nt], a[1], b);
            }
        }
        // combine: z = E + diff + b1 ; h = relu(z) -> tf32 -> s_hz (in place)
#pragma unroll
        for (int nt = 0; nt < 8; ++nt) {
            int c = wn * 64 + nt * 8 + 2 * tq;
            float bv0 = __ldg(&b1[c]);
            float bv1 = __ldg(&b1[c + 1]);
#pragma unroll
            for (int mt = 0; mt < 2; ++mt) {
#pragma unroll
                for (int h2 = 0; h2 < 2; ++h2) {
                    int r = wm * 32 + mt * 16 + g + h2 * 8;
                    float2 d = *(float2*)&s_hz[r * 132 + c];
                    float z0 = acc[mt][nt][h2 * 2 + 0] + d.x + bv0;
                    float z1 = acc[mt][nt][h2 * 2 + 1] + d.y + bv1;
                    unsigned h0 = f2tf(fmaxf(z0, 0.f));
                    unsigned h1 = f2tf(fmaxf(z1, 0.f));
                    float2 hh = {__uint_as_float(h0), __uint_as_float(h1)};
                    *(float2*)&s_hz[r * 132 + c] = hh;
                }
            }
        }
        __syncthreads();

        // ---- layer 2: out = h @ W2  (M=128, N=128, K=128) ----
#pragma unroll
        for (int mt = 0; mt < 2; ++mt)
#pragma unroll
            for (int nt = 0; nt < 8; ++nt)
#pragma unroll
                for (int j = 0; j < 4; ++j) acc[mt][nt][j] = 0.f;

        for (int chunk = 0; chunk < 4; ++chunk) {
            for (int i = tid; i < 1024; i += 256) {   // stage W2T [128n][32k] chunk
                int n = i >> 3, q = i & 7;
                *(float4*)&s_w[n * 36 + q * 4] =
                    *(const float4*)&g_W2T[pass * 16384 + n * 128 + chunk * 32 + q * 4];
            }
            __syncthreads();
#pragma unroll
            for (int kt = 0; kt < 4; ++kt) {
                int k0 = chunk * 32 + kt * 8;
                unsigned a[2][4];
#pragma unroll
                for (int mt = 0; mt < 2; ++mt) {
                    int r = wm * 32 + mt * 16 + g;
                    a[mt][0] = u_hz[r * 132 + k0 + tq];
                    a[mt][1] = u_hz[(r + 8) * 132 + k0 + tq];
                    a[mt][2] = u_hz[r * 132 + k0 + tq + 4];
                    a[mt][3] = u_hz[(r + 8) * 132 + k0 + tq + 4];
                }
#pragma unroll
                for (int nt = 0; nt < 8; ++nt) {
                    int c = wn * 64 + nt * 8 + g;
                    unsigned b[2];
                    b[0] = u_w[c * 36 + kt * 8 + tq];
                    b[1] = u_w[c * 36 + kt * 8 + tq + 4];
                    mma_tf32(acc[0][nt], a[0], b);
                    mma_tf32(acc[1][nt], a[1], b);
                }
            }
            __syncthreads();
        }

        if (pass == 0) {
#pragma unroll
            for (int nt = 0; nt < 8; ++nt) {
                int c = wn * 64 + nt * 8 + 2 * tq;
                float bv0 = __ldg(&b2[c]);
                float bv1 = __ldg(&b2[c + 1]);
                keep[0][nt][0] = acc[0][nt][0] + bv0;
                keep[0][nt][1] = acc[0][nt][1] + bv1;
                keep[0][nt][2] = acc[0][nt][2] + bv0;
                keep[0][nt][3] = acc[0][nt][3] + bv1;
                keep[1][nt][0] = acc[1][nt][0] + bv0;
                keep[1][nt][1] = acc[1][nt][1] + bv1;
                keep[1][nt][2] = acc[1][nt][2] + bv0;
                keep[1][nt][3] = acc[1][nt][3] + bv1;
            }
        } else {
            // att = sigmoid(out + b2); prod = msg * att -> s_hz
#pragma unroll
            for (int nt = 0; nt < 8; ++nt) {
                int c = wn * 64 + nt * 8 + 2 * tq;
                float bv0 = __ldg(&b2[c]);
                float bv1 = __ldg(&b2[c + 1]);
#pragma unroll
                for (int mt = 0; mt < 2; ++mt) {
#pragma unroll
                    for (int h2 = 0; h2 < 2; ++h2) {
                        int r = wm * 32 + mt * 16 + g + h2 * 8;
                        float z0 = acc[mt][nt][h2 * 2 + 0] + bv0;
                        float z1 = acc[mt][nt][h2 * 2 + 1] + bv1;
                        float a0 = 1.f / (1.f + __expf(-z0));
                        float a1 = 1.f / (1.f + __expf(-z1));
                        float2 pr;
                        pr.x = keep[mt][nt][h2 * 2 + 0] * a0;
                        pr.y = keep[mt][nt][h2 * 2 + 1] * a1;
                        *(float2*)&s_hz[r * 132 + c] = pr;
                    }
                }
            }
            __syncthreads();
            int tx = tid & 15, ty = tid >> 4;
#pragma unroll
            for (int r = 0; r < 8; ++r) {
                int e = ty * 8 + r;
                float* ap = g_agg + (size_t)s_dst[e] * 128 + tx * 8;
                const float* pp = &s_hz[e * 132 + tx * 8];
                red_add4(ap, pp[0], pp[1], pp[2], pp[3]);
                red_add4(ap + 4, pp[4], pp[5], pp[6], pp[7]);
            }
        }
    }
}

// ---------------- GRU GEMMs (fp32) ----------------
__global__ void __launch_bounds__(256) gemm_tn(const float* __restrict__ Ain,
                                               const float* __restrict__ W,
                                               const float* __restrict__ bias, int mode) {
    __shared__ float As[16][136];
    __shared__ float Bs[16][136];
    const float* A = mode ? g_agg : Ain;
    float* G = mode ? g_G1 : g_G2;
    int tid = threadIdx.x, tx = tid & 15, ty = tid >> 4;
    int rb = blockIdx.x * 128;
    int jb = blockIdx.y * 128;
    float acc[8][8];
#pragma unroll
    for (int r = 0; r < 8; ++r)
#pragma unroll
        for (int j = 0; j < 8; ++j) acc[r][j] = 0.f;

    for (int kt = 0; kt < 8; ++kt) {
        int k0 = kt * 16;
        __syncthreads();
        for (int i = tid; i < 2048; i += 256) {
            int row = i >> 4, k = i & 15;
            int v = rb + row;
            As[k][row] = (v < Nn) ? A[(size_t)v * 128 + k0 + k] : 0.f;
        }
        for (int i = tid; i < 2048; i += 256) {
            int j = i >> 4, k = i & 15;
            Bs[k][j] = W[(size_t)(jb + j) * 128 + k0 + k];
        }
        __syncthreads();
#pragma unroll
        for (int k = 0; k < 16; ++k) {
            float a[8], b[8];
            *(float4*)(a)     = *(float4*)&As[k][ty * 8];
            *(float4*)(a + 4) = *(float4*)&As[k][ty * 8 + 4];
            *(float4*)(b)     = *(float4*)&Bs[k][tx * 8];
            *(float4*)(b + 4) = *(float4*)&Bs[k][tx * 8 + 4];
#pragma unroll
            for (int r = 0; r < 8; ++r)
#pragma unroll
                for (int j = 0; j < 8; ++j) acc[r][j] = fmaf(a[r], b[j], acc[r][j]);
        }
    }
    float br[8];
#pragma unroll
    for (int j = 0; j < 8; ++j) br[j] = bias[jb + tx * 8 + j];
#pragma unroll
    for (int r = 0; r < 8; ++r) {
        int v = rb + ty * 8 + r;
        if (v < Nn) {
            float4 o0 = {acc[r][0] + br[0], acc[r][1] + br[1], acc[r][2] + br[2], acc[r][3] + br[3]};
            float4 o1 = {acc[r][4] + br[4], acc[r][5] + br[5], acc[r][6] + br[6], acc[r][7] + br[7]};
            *(float4*)&G[(size_t)v * 384 + jb + tx * 8]     = o0;
            *(float4*)&G[(size_t)v * 384 + jb + tx * 8 + 4] = o1;
        }
    }
}

// ---------------- gate / output ----------------
__device__ __forceinline__ float gatef(float ir, float iz, float in_, float hr, float hz, float hn, float s) {
    float r = 1.f / (1.f + __expf(-(ir + hr)));
    float z = 1.f / (1.f + __expf(-(iz + hz)));
    float n = tanhf(in_ + r * hn);
    return (1.f - z) * n + z * s;
}
__global__ void gate_kernel(const float* __restrict__ state, float* __restrict__ out) {
    int i = blockIdx.x * blockDim.x + threadIdx.x;
    int v = i >> 5;
    int q = (i & 31) * 4;
    const float4 ir = *(const float4*)&g_G1[(size_t)v * 384 + q];
    const float4 iz = *(const float4*)&g_G1[(size_t)v * 384 + 128 + q];
    const float4 in_ = *(const float4*)&g_G1[(size_t)v * 384 + 256 + q];
    const float4 hr = *(const float4*)&g_G2[(size_t)v * 384 + q];
    const float4 hz = *(const float4*)&g_G2[(size_t)v * 384 + 128 + q];
    const float4 hn = *(const float4*)&g_G2[(size_t)v * 384 + 256 + q];
    const float4 s  = *(const float4*)&state[(size_t)v * 128 + q];
    float4 o;
    o.x = gatef(ir.x, iz.x, in_.x, hr.x, hz.x, hn.x, s.x);
    o.y = gatef(ir.y, iz.y, in_.y, hr.y, hz.y, hn.y, s.y);
    o.z = gatef(ir.z, iz.z, in_.z, hr.z, hz.z, hn.z, s.z);
    o.w = gatef(ir.w, iz.w, in_.w, hr.w, hz.w, hn.w, s.w);
    *(float4*)&out[(size_t)v * 128 + q] = o;
}

// ---------------- launch ----------------
extern "C" void kernel_launch(void* const* d_in, const int* in_sizes, int n_in,
                              void* d_out, int out_size) {
    const float* node_feat = (const float*)d_in[0];
    const int*   edge      = (const int*)d_in[1];
    const float* edge_feat = (const float*)d_in[2];
    const float* node_attr = (const float*)d_in[3];
    const float* edge_attr = (const float*)d_in[4];
    const float* msg_w1 = (const float*)d_in[5];
    const float* msg_b1 = (const float*)d_in[6];
    const float* msg_w2 = (const float*)d_in[7];
    const float* msg_b2 = (const float*)d_in[8];
    const float* att_w1 = (const float*)d_in[9];
    const float* att_b1 = (const float*)d_in[10];
    const float* att_w2 = (const float*)d_in[11];
    const float* att_b2 = (const float*)d_in[12];
    const float* gru_w_ih = (const float*)d_in[13];
    const float* gru_w_hh = (const float*)d_in[14];
    const float* gru_b_ih = (const float*)d_in[15];
    const float* gru_b_hh = (const float*)d_in[16];
    float* out = (float*)d_out;

    cudaFuncSetAttribute(edge_kernel, cudaFuncAttributeMaxDynamicSharedMemorySize, SMEM_EDGE_BYTES);

    prep_weights<<<290, 256>>>(msg_w1, att_w1);
    prep_mma<<<160, 256>>>(msg_w1, att_w1, msg_w2, att_w2);
    clear_agg<<<6250, 256>>>();
    node_pre<<<dim3(391, 2), 256>>>(node_feat, edge_attr, node_attr);
    gemm_tn<<<dim3(391, 3), 256>>>(node_feat, gru_w_hh, gru_b_hh, 0);   // G2 = state @ Whh^T
    edge_kernel<<<6250, 256, SMEM_EDGE_BYTES>>>(edge, edge_feat,
                                                msg_b1, msg_b2, att_b1, att_b2);
    gemm_tn<<<dim3(391, 3), 256>>>(nullptr, gru_w_ih, gru_b_ih, 1);     // G1 = agg @ Wih^T
    gate_kernel<<<6250, 256>>>(node_feat, out);
}